// round 3
// baseline (speedup 1.0000x reference)
#include <cuda_runtime.h>

// Problem: ICGP_Convnp — RBF-smoothed feature aggregation.
// out[b,m,k,c] = sum_n feat[b,n,k,c] * exp(-0.5*((xa[b,n,c]-xt[b,m,c])/std[k,c])^2)
// Shapes fixed by the dataset: B=8, N1=N2=1024, D=1, K=5, C=3.

constexpr int B_  = 8;
constexpr int N1_ = 1024;
constexpr int N2_ = 1024;
constexpr int K_  = 5;
constexpr int C_  = 3;

constexpr int WARPS   = 8;            // warps per block, one m per warp
constexpr int THREADS = WARPS * 32;
constexpr int FSTRIDE = 20;           // padded floats/row for features: slot k*4+c
                                      // (20-word stride => conflict-free LDS.128 at lane-strided n)
constexpr int XSTRIDE = 4;            // padded floats/row for xa
constexpr int SMEM_FLOATS = N1_ * XSTRIDE + N1_ * FSTRIDE;  // 4096 + 20480 = 24576 (96 KB)

__device__ __forceinline__ float ex2f(float x) {
    float y;
    asm("ex2.approx.ftz.f32 %0, %1;" : "=f"(y) : "f"(x));
    return y;
}

__global__ __launch_bounds__(THREADS, 2)
void icgp_kernel(const float* __restrict__ xa, const float* __restrict__ feat,
                 const float* __restrict__ xt, const float* __restrict__ lstd,
                 float* __restrict__ out)
{
    extern __shared__ float smem[];
    float* s_xa = smem;                      // [N1][4]
    float* s_ft = smem + N1_ * XSTRIDE;      // [N1][20], slot k*4+c
    __shared__ float s_coef[15];
    __shared__ int   s_uni;

    const int b    = blockIdx.y;
    const int tid  = threadIdx.x;
    const int wid  = tid >> 5;
    const int lane = tid & 31;
    const int m    = blockIdx.x * WARPS + wid;

    // coef[k,c] = -0.5*log2(e) / (exp(log_std)+eps)^2   (exp2-domain RBF)
    if (tid < 15) {
        float s = __expf(lstd[tid]) + 1e-6f;
        s_coef[tid] = -0.72134752044448170f / (s * s);
    }
    __syncthreads();
    if (tid == 0) {
        int u = 1;
        #pragma unroll
        for (int i = 1; i < 15; i++)
            u &= (__float_as_int(s_coef[i]) == __float_as_int(s_coef[0]));
        s_uni = u;
    }

    // Stage xa[b] and features[b] into padded shared (coalesced-ish, one-time).
    const float* xa_b = xa + (size_t)b * N1_ * C_;
    for (int n = tid; n < N1_; n += THREADS) {
        s_xa[n * XSTRIDE + 0] = xa_b[n * 3 + 0];
        s_xa[n * XSTRIDE + 1] = xa_b[n * 3 + 1];
        s_xa[n * XSTRIDE + 2] = xa_b[n * 3 + 2];
        s_xa[n * XSTRIDE + 3] = 0.f;
    }
    const float* f_b = feat + (size_t)b * N1_ * K_ * C_;
    for (int n = tid; n < N1_; n += THREADS) {
        #pragma unroll
        for (int k = 0; k < K_; k++) {
            #pragma unroll
            for (int c = 0; c < C_; c++)
                s_ft[n * FSTRIDE + k * 4 + c] = f_b[n * 15 + k * 3 + c];
        }
    }
    __syncthreads();

    const float* xt_bm = xt + ((size_t)b * N2_ + m) * C_;
    const float t0 = xt_bm[0], t1 = xt_bm[1], t2 = xt_bm[2];

    float acc[15];
    #pragma unroll
    for (int i = 0; i < 15; i++) acc[i] = 0.f;

    if (s_uni) {
        // Fast path: all bandwidths identical -> weight depends only on channel c.
        const float c0 = s_coef[0];
        for (int n = lane; n < N1_; n += 32) {
            float4 a = *reinterpret_cast<const float4*>(&s_xa[n * XSTRIDE]);
            float d0 = a.x - t0, d1 = a.y - t1, d2 = a.z - t2;
            float w0 = ex2f(d0 * d0 * c0);
            float w1 = ex2f(d1 * d1 * c0);
            float w2 = ex2f(d2 * d2 * c0);
            #pragma unroll
            for (int k = 0; k < K_; k++) {
                float4 f = *reinterpret_cast<const float4*>(&s_ft[n * FSTRIDE + k * 4]);
                acc[k*3+0] = fmaf(f.x, w0, acc[k*3+0]);
                acc[k*3+1] = fmaf(f.y, w1, acc[k*3+1]);
                acc[k*3+2] = fmaf(f.z, w2, acc[k*3+2]);
            }
        }
    } else {
        // General path: per-(k,c) bandwidth, 15 exps per n.
        float cf[15];
        #pragma unroll
        for (int i = 0; i < 15; i++) cf[i] = s_coef[i];
        for (int n = lane; n < N1_; n += 32) {
            float4 a = *reinterpret_cast<const float4*>(&s_xa[n * XSTRIDE]);
            float d0 = a.x - t0, d1 = a.y - t1, d2 = a.z - t2;
            float q0 = d0 * d0, q1 = d1 * d1, q2 = d2 * d2;
            #pragma unroll
            for (int k = 0; k < K_; k++) {
                float4 f = *reinterpret_cast<const float4*>(&s_ft[n * FSTRIDE + k * 4]);
                float w0 = ex2f(q0 * cf[k*3+0]);
                float w1 = ex2f(q1 * cf[k*3+1]);
                float w2 = ex2f(q2 * cf[k*3+2]);
                acc[k*3+0] = fmaf(f.x, w0, acc[k*3+0]);
                acc[k*3+1] = fmaf(f.y, w1, acc[k*3+1]);
                acc[k*3+2] = fmaf(f.z, w2, acc[k*3+2]);
            }
        }
    }

    // Warp tree-reduction of the 15 accumulators over the n-lanes.
    #pragma unroll
    for (int i = 0; i < 15; i++) {
        #pragma unroll
        for (int off = 16; off > 0; off >>= 1)
            acc[i] += __shfl_xor_sync(0xffffffffu, acc[i], off);
    }
    if (lane == 0) {
        float* o = out + ((size_t)b * N2_ + m) * (K_ * C_);
        #pragma unroll
        for (int i = 0; i < 15; i++) o[i] = acc[i];
    }
}

extern "C" void kernel_launch(void* const* d_in, const int* in_sizes, int n_in,
                              void* d_out, int out_size)
{
    const float* xa   = (const float*)d_in[0];
    const float* feat = (const float*)d_in[1];
    const float* xt   = (const float*)d_in[2];
    const float* lstd = (const float*)d_in[3];
    float* out = (float*)d_out;

    const size_t smem = SMEM_FLOATS * sizeof(float);   // 96 KB dynamic
    cudaFuncSetAttribute(icgp_kernel, cudaFuncAttributeMaxDynamicSharedMemorySize, (int)smem);

    dim3 grid(N2_ / WARPS, B_);   // (128, 8) blocks
    icgp_kernel<<<grid, THREADS, smem>>>(xa, feat, xt, lstd, out);
}

// round 6
// speedup vs baseline: 1.6229x; 1.6229x over previous
#include <cuda_runtime.h>

// ICGP_Convnp: out[b,m,k,c] = sum_n feat[b,n,k,c] * exp(-0.5*((xa[b,n,c]-xt[b,m,c])/std[k,c])^2)
// B=8, N1=N2=1024, D=1, K=5, C=3.
// Mapping: lane -> m (32 m per warp, xt in regs), warp -> n-chunk (128 n each),
// so all shared loads in the hot loop are warp-broadcast (conflict-free, 1 wavefront).

constexpr int B_  = 8;
constexpr int N1_ = 1024;
constexpr int N2_ = 1024;
constexpr int K_  = 5;
constexpr int C_  = 3;

constexpr int WARPS    = 8;
constexpr int THREADS  = WARPS * 32;       // 256
constexpr int NCHUNK   = N1_ / WARPS;      // 128 n per warp
constexpr int M_BLK    = 32;               // m's per block (one per lane)
constexpr int FSTRIDE  = 20;               // padded feature row: slot k*4+c
constexpr int XSTRIDE  = 4;
constexpr int SMEM_FLOATS = N1_ * XSTRIDE + N1_ * FSTRIDE;  // 24576 floats = 96 KB

__device__ __forceinline__ float ex2f(float x) {
    float y;
    asm("ex2.approx.ftz.f32 %0, %1;" : "=f"(y) : "f"(x));
    return y;
}

__global__ __launch_bounds__(THREADS, 2)
void icgp_kernel(const float* __restrict__ xa, const float* __restrict__ feat,
                 const float* __restrict__ xt, const float* __restrict__ lstd,
                 float* __restrict__ out)
{
    extern __shared__ float smem[];
    float* s_xa = smem;                      // [N1][4]
    float* s_ft = smem + N1_ * XSTRIDE;      // [N1][20], slot k*4+c
    __shared__ float s_coef[15];
    __shared__ int   s_uni;

    const int b      = blockIdx.y;
    const int tid    = threadIdx.x;
    const int wid    = tid >> 5;
    const int lane   = tid & 31;
    const int m_base = blockIdx.x * M_BLK;
    const int m      = m_base + lane;

    // coef[k,c] = -0.5*log2(e) / (exp(log_std)+eps)^2   (exp2-domain RBF)
    if (tid < 15) {
        float s = __expf(lstd[tid]) + 1e-6f;
        s_coef[tid] = -0.72134752044448170f / (s * s);
    }
    __syncthreads();
    if (tid == 0) {
        int u = 1;
        #pragma unroll
        for (int i = 1; i < 15; i++)
            u &= (__float_as_int(s_coef[i]) == __float_as_int(s_coef[0]));
        s_uni = u;
    }

    // Stage xa[b] into padded shared.
    const float* xa_b = xa + (size_t)b * N1_ * C_;
    for (int n = tid; n < N1_; n += THREADS) {
        s_xa[n * XSTRIDE + 0] = xa_b[n * 3 + 0];
        s_xa[n * XSTRIDE + 1] = xa_b[n * 3 + 1];
        s_xa[n * XSTRIDE + 2] = xa_b[n * 3 + 2];
        s_xa[n * XSTRIDE + 3] = 0.f;
    }
    // Stage features[b] fully-coalesced: linear index -> padded slot.
    const float* f_b = feat + (size_t)b * N1_ * K_ * C_;
    for (int i = tid; i < N1_ * 15; i += THREADS) {
        int n = i / 15, s = i - n * 15;
        s_ft[n * FSTRIDE + (s / 3) * 4 + (s % 3)] = f_b[i];
    }
    __syncthreads();

    // Per-lane target point (registers).
    const float* xt_bm = xt + ((size_t)b * N2_ + m) * C_;
    const float t0 = xt_bm[0], t1 = xt_bm[1], t2 = xt_bm[2];

    float acc[15];
    #pragma unroll
    for (int i = 0; i < 15; i++) acc[i] = 0.f;

    const int n0 = wid * NCHUNK;

    if (s_uni) {
        // Fast path: all (k,c) bandwidths identical -> weight depends only on c.
        const float c0 = s_coef[0];
        #pragma unroll 2
        for (int n = n0; n < n0 + NCHUNK; n++) {
            float4 a = *reinterpret_cast<const float4*>(&s_xa[n * XSTRIDE]);   // broadcast
            float d0 = a.x - t0, d1 = a.y - t1, d2 = a.z - t2;
            float w0 = ex2f(d0 * d0 * c0);
            float w1 = ex2f(d1 * d1 * c0);
            float w2 = ex2f(d2 * d2 * c0);
            #pragma unroll
            for (int k = 0; k < K_; k++) {
                float4 f = *reinterpret_cast<const float4*>(&s_ft[n * FSTRIDE + k * 4]);  // broadcast
                acc[k*3+0] = fmaf(f.x, w0, acc[k*3+0]);
                acc[k*3+1] = fmaf(f.y, w1, acc[k*3+1]);
                acc[k*3+2] = fmaf(f.z, w2, acc[k*3+2]);
            }
        }
    } else {
        // General path: per-(k,c) bandwidth, 15 exps per (n, m).
        float cf[15];
        #pragma unroll
        for (int i = 0; i < 15; i++) cf[i] = s_coef[i];
        for (int n = n0; n < n0 + NCHUNK; n++) {
            float4 a = *reinterpret_cast<const float4*>(&s_xa[n * XSTRIDE]);
            float d0 = a.x - t0, d1 = a.y - t1, d2 = a.z - t2;
            float q0 = d0 * d0, q1 = d1 * d1, q2 = d2 * d2;
            #pragma unroll
            for (int k = 0; k < K_; k++) {
                float4 f = *reinterpret_cast<const float4*>(&s_ft[n * FSTRIDE + k * 4]);
                acc[k*3+0] = fmaf(f.x, ex2f(q0 * cf[k*3+0]), acc[k*3+0]);
                acc[k*3+1] = fmaf(f.y, ex2f(q1 * cf[k*3+1]), acc[k*3+1]);
                acc[k*3+2] = fmaf(f.z, ex2f(q2 * cf[k*3+2]), acc[k*3+2]);
            }
        }
    }

    // Cross-warp reduction: 8 partials per (m-lane, i). Reuse feature smem.
    __syncthreads();                         // all warps done reading s_ft
    float* red = s_ft;                       // [8][32][16] = 4096 floats
    {
        float* dst = &red[(wid * 32 + lane) * 16];
        #pragma unroll
        for (int i = 0; i < 15; i++) dst[i] = acc[i];
    }
    __syncthreads();

    // 480 outputs per block; 256 threads -> strided loop (2 iterations max).
    for (int o = tid; o < M_BLK * 15; o += THREADS) {
        int lane_m = o / 15, i = o - lane_m * 15;
        float s = 0.f;
        #pragma unroll
        for (int w = 0; w < WARPS; w++)
            s += red[(w * 32 + lane_m) * 16 + i];
        out[((size_t)b * N2_ + m_base) * 15 + o] = s;
    }
}

extern "C" void kernel_launch(void* const* d_in, const int* in_sizes, int n_in,
                              void* d_out, int out_size)
{
    const float* xa   = (const float*)d_in[0];
    const float* feat = (const float*)d_in[1];
    const float* xt   = (const float*)d_in[2];
    const float* lstd = (const float*)d_in[3];
    float* out = (float*)d_out;

    const size_t smem = SMEM_FLOATS * sizeof(float);   // 96 KB dynamic
    cudaFuncSetAttribute(icgp_kernel, cudaFuncAttributeMaxDynamicSharedMemorySize, (int)smem);

    dim3 grid(N2_ / M_BLK, B_);   // (32, 8) = 256 blocks
    icgp_kernel<<<grid, THREADS, smem>>>(xa, feat, xt, lstd, out);
}

// round 9
// speedup vs baseline: 1.8733x; 1.1543x over previous
#include <cuda_runtime.h>
#include <cstdint>

// ICGP_Convnp: out[b,m,k,c] = sum_n feat[b,n,k,c] * exp(-0.5*((xa[b,n,c]-xt[b,m,c])/std[k,c])^2)
// B=8, N1=N2=1024, D=1, K=5, C=3.
// lane -> m (broadcast LDS), warp -> n-chunk; k-loop as 8 packed fma.rn.f32x2.

constexpr int B_  = 8;
constexpr int N1_ = 1024;
constexpr int N2_ = 1024;

constexpr int WARPS    = 16;
constexpr int THREADS  = WARPS * 32;       // 512
constexpr int NCHUNK   = N1_ / WARPS;      // 64 n per warp
constexpr int M_BLK    = 32;               // one m per lane
constexpr int FSTRIDE  = 16;               // feature row padded 15 -> 16 floats (64B)
constexpr int XSTRIDE  = 4;
constexpr int SMEM_FLOATS = N1_ * XSTRIDE + N1_ * FSTRIDE;  // 4096 + 16384 = 20480 (80 KB)

__device__ __forceinline__ float ex2f(float x) {
    float y;
    asm("ex2.approx.ftz.f32 %0, %1;" : "=f"(y) : "f"(x));
    return y;
}
__device__ __forceinline__ uint64_t packf2(float lo, float hi) {
    uint64_t r;
    asm("mov.b64 %0, {%1, %2};" : "=l"(r) : "f"(lo), "f"(hi));
    return r;
}
__device__ __forceinline__ uint64_t fma2(uint64_t a, uint64_t b, uint64_t c) {
    uint64_t d;
    asm("fma.rn.f32x2 %0, %1, %2, %3;" : "=l"(d) : "l"(a), "l"(b), "l"(c));
    return d;
}
__device__ __forceinline__ void unpackf2(uint64_t v, float& lo, float& hi) {
    asm("mov.b64 {%0, %1}, %2;" : "=f"(lo), "=f"(hi) : "l"(v));
}

__global__ __launch_bounds__(THREADS, 2)
void icgp_kernel(const float* __restrict__ xa, const float* __restrict__ feat,
                 const float* __restrict__ xt, const float* __restrict__ lstd,
                 float* __restrict__ out)
{
    extern __shared__ float smem[];
    float* s_xa = smem;                      // [N1][4]  raw xa
    float* s_ft = smem + N1_ * XSTRIDE;      // [N1][16], slots 0..14 = (k,c), slot 15 = 0
    __shared__ float s_coef[15];
    __shared__ int   s_uni;

    const int b      = blockIdx.y;
    const int tid    = threadIdx.x;
    const int wid    = tid >> 5;
    const int lane   = tid & 31;
    const int m_base = blockIdx.x * M_BLK;
    const int m      = m_base + lane;

    // coef[k,c] = -0.5*log2(e) / (exp(log_std)+eps)^2
    if (tid < 15) {
        float s = __expf(lstd[tid]) + 1e-6f;
        s_coef[tid] = -0.72134752044448170f / (s * s);
    }
    __syncthreads();
    if (tid == 0) {
        int u = 1;
        #pragma unroll
        for (int i = 1; i < 15; i++)
            u &= (__float_as_int(s_coef[i]) == __float_as_int(s_coef[0]));
        s_uni = u;
    }

    // Stage xa[b] (raw) into padded shared.
    const float* xa_b = xa + (size_t)b * N1_ * 3;
    for (int n = tid; n < N1_; n += THREADS) {
        s_xa[n * XSTRIDE + 0] = xa_b[n * 3 + 0];
        s_xa[n * XSTRIDE + 1] = xa_b[n * 3 + 1];
        s_xa[n * XSTRIDE + 2] = xa_b[n * 3 + 2];
        s_xa[n * XSTRIDE + 3] = 0.f;
    }
    // Stage features[b]: 15 floats -> 16-slot row, slot 15 zeroed.
    const float* f_b = feat + (size_t)b * N1_ * 15;
    for (int i = tid; i < N1_ * FSTRIDE; i += THREADS) {
        int n = i >> 4, s = i & 15;
        s_ft[i] = (s < 15) ? f_b[n * 15 + s] : 0.f;
    }
    __syncthreads();

    // Per-lane target point.
    const float* xt_bm = xt + ((size_t)b * N2_ + m) * 3;
    const float t0r = xt_bm[0], t1r = xt_bm[1], t2r = xt_bm[2];

    const int n0 = wid * NCHUNK;

    uint64_t acc2[8];
    #pragma unroll
    for (int i = 0; i < 8; i++) acc2[i] = 0ull;
    float acc_s[15];   // general path only
    #pragma unroll
    for (int i = 0; i < 15; i++) acc_s[i] = 0.f;

    const int uni = s_uni;
    if (uni) {
        // w_c = exp2(-( (a_c - t_c)*s )^2 ),  s = sqrt(-c0)
        const float s = sqrtf(-s_coef[0]);
        const float t0 = t0r * s, t1 = t1r * s, t2 = t2r * s;
        #pragma unroll 2
        for (int n = n0; n < n0 + NCHUNK; n++) {
            float4 a = *reinterpret_cast<const float4*>(&s_xa[n * XSTRIDE]);  // broadcast
            float u0 = fmaf(a.x, s, -t0);
            float u1 = fmaf(a.y, s, -t1);
            float u2 = fmaf(a.z, s, -t2);
            float w0 = ex2f(u0 * -u0);
            float w1 = ex2f(u1 * -u1);
            float w2 = ex2f(u2 * -u2);
            // packed weight pattern over 16-slot row: A B C A B C A B
            uint64_t WA = packf2(w0, w1);
            uint64_t WB = packf2(w2, w0);
            uint64_t WC = packf2(w1, w2);
            const uint64_t* f2p = reinterpret_cast<const uint64_t*>(&s_ft[n * FSTRIDE]); // broadcast
            acc2[0] = fma2(f2p[0], WA, acc2[0]);
            acc2[1] = fma2(f2p[1], WB, acc2[1]);
            acc2[2] = fma2(f2p[2], WC, acc2[2]);
            acc2[3] = fma2(f2p[3], WA, acc2[3]);
            acc2[4] = fma2(f2p[4], WB, acc2[4]);
            acc2[5] = fma2(f2p[5], WC, acc2[5]);
            acc2[6] = fma2(f2p[6], WA, acc2[6]);
            acc2[7] = fma2(f2p[7], WB, acc2[7]);  // slot15 feature = 0
        }
    } else {
        // General path: per-(k,c) bandwidth, scalar.
        float cf[15];
        #pragma unroll
        for (int i = 0; i < 15; i++) cf[i] = s_coef[i];
        for (int n = n0; n < n0 + NCHUNK; n++) {
            float4 a = *reinterpret_cast<const float4*>(&s_xa[n * XSTRIDE]);
            float d0 = a.x - t0r, d1 = a.y - t1r, d2 = a.z - t2r;
            float q0 = d0 * d0, q1 = d1 * d1, q2 = d2 * d2;
            #pragma unroll
            for (int k = 0; k < 5; k++) {
                float fx = s_ft[n * FSTRIDE + k * 3 + 0];
                float fy = s_ft[n * FSTRIDE + k * 3 + 1];
                float fz = s_ft[n * FSTRIDE + k * 3 + 2];
                acc_s[k*3+0] = fmaf(fx, ex2f(q0 * cf[k*3+0]), acc_s[k*3+0]);
                acc_s[k*3+1] = fmaf(fy, ex2f(q1 * cf[k*3+1]), acc_s[k*3+1]);
                acc_s[k*3+2] = fmaf(fz, ex2f(q2 * cf[k*3+2]), acc_s[k*3+2]);
            }
        }
    }

    // Merge packed accumulators into scalar form.
    if (uni) {
        #pragma unroll
        for (int j = 0; j < 8; j++) {
            float lo, hi;
            unpackf2(acc2[j], lo, hi);
            if (2*j     < 15) acc_s[2*j]     = lo;
            if (2*j + 1 < 15) acc_s[2*j + 1] = hi;
        }
    }

    // Cross-warp reduction: 16 partials per (m-lane, i). Reuse feature smem.
    __syncthreads();
    float* red = s_ft;                       // [16][32][16] = 8192 floats
    {
        float* dst = &red[(wid * 32 + lane) * 16];
        #pragma unroll
        for (int i = 0; i < 15; i++) dst[i] = acc_s[i];
    }
    __syncthreads();

    // 480 outputs per block; 512 threads -> one each.
    if (tid < M_BLK * 15) {
        int lane_m = tid / 15, i = tid - lane_m * 15;
        float s = 0.f;
        #pragma unroll
        for (int w = 0; w < WARPS; w++)
            s += red[(w * 32 + lane_m) * 16 + i];
        out[((size_t)b * N2_ + m_base) * 15 + tid] = s;
    }
}

extern "C" void kernel_launch(void* const* d_in, const int* in_sizes, int n_in,
                              void* d_out, int out_size)
{
    const float* xa   = (const float*)d_in[0];
    const float* feat = (const float*)d_in[1];
    const float* xt   = (const float*)d_in[2];
    const float* lstd = (const float*)d_in[3];
    float* out = (float*)d_out;

    const size_t smem = SMEM_FLOATS * sizeof(float);   // 80 KB dynamic
    cudaFuncSetAttribute(icgp_kernel, cudaFuncAttributeMaxDynamicSharedMemorySize, (int)smem);

    dim3 grid(N2_ / M_BLK, B_);   // (32, 8) = 256 blocks
    icgp_kernel<<<grid, THREADS, smem>>>(xa, feat, xt, lstd, out);
}

// round 13
// speedup vs baseline: 2.2973x; 1.2264x over previous
#include <cuda_runtime.h>
#include <cstdint>

// ICGP_Convnp: out[b,m,k,c] = sum_n feat[b,n,k,c] * exp(-0.5*((xa[b,n,c]-xt[b,m,c])/std[k,c])^2)
// B=8, N1=N2=1024, D=1, K=5, C=3.
// lane -> 2 m's (broadcast LDS serves 64 outputs), warp -> n-chunk; k-loop = packed fma.rn.f32x2.

constexpr int B_  = 8;
constexpr int N1_ = 1024;
constexpr int N2_ = 1024;

constexpr int WARPS    = 16;
constexpr int THREADS  = WARPS * 32;       // 512
constexpr int NCHUNK   = N1_ / WARPS;      // 64 n per warp
constexpr int M_BLK    = 64;               // 2 m per lane
constexpr int FSTRIDE  = 16;               // feature row padded 15 -> 16 floats (64B)
constexpr int XSTRIDE  = 4;
constexpr int SMEM_FLOATS = N1_ * XSTRIDE + N1_ * FSTRIDE;  // 20480 floats = 80 KB

__device__ __forceinline__ float ex2f(float x) {
    float y;
    asm("ex2.approx.ftz.f32 %0, %1;" : "=f"(y) : "f"(x));
    return y;
}
__device__ __forceinline__ uint64_t packf2(float lo, float hi) {
    uint64_t r;
    asm("mov.b64 %0, {%1, %2};" : "=l"(r) : "f"(lo), "f"(hi));
    return r;
}
__device__ __forceinline__ uint64_t fma2(uint64_t a, uint64_t b, uint64_t c) {
    uint64_t d;
    asm("fma.rn.f32x2 %0, %1, %2, %3;" : "=l"(d) : "l"(a), "l"(b), "l"(c));
    return d;
}
__device__ __forceinline__ void unpackf2(uint64_t v, float& lo, float& hi) {
    asm("mov.b64 {%0, %1}, %2;" : "=f"(lo), "=f"(hi) : "l"(v));
}

__global__ __launch_bounds__(THREADS, 1)
void icgp_kernel(const float* __restrict__ xa, const float* __restrict__ feat,
                 const float* __restrict__ xt, const float* __restrict__ lstd,
                 float* __restrict__ out)
{
    extern __shared__ float smem[];
    float* s_xa = smem;                      // [N1][4]  raw xa
    float* s_ft = smem + N1_ * XSTRIDE;      // [N1][16], slots 0..14 = (k,c), slot 15 = 0
    __shared__ float s_coef[15];
    __shared__ int   s_uni;

    const int b      = blockIdx.y;
    const int tid    = threadIdx.x;
    const int wid    = tid >> 5;
    const int lane   = tid & 31;
    const int m_base = blockIdx.x * M_BLK;
    const int m0     = m_base + lane;        // lane's first m
    const int m1     = m0 + 32;              // lane's second m

    // coef[k,c] = -0.5*log2(e) / (exp(log_std)+eps)^2
    if (tid < 15) {
        float s = __expf(lstd[tid]) + 1e-6f;
        s_coef[tid] = -0.72134752044448170f / (s * s);
    }
    __syncthreads();
    if (tid == 0) {
        int u = 1;
        #pragma unroll
        for (int i = 1; i < 15; i++)
            u &= (__float_as_int(s_coef[i]) == __float_as_int(s_coef[0]));
        s_uni = u;
    }

    // Stage xa[b] into padded shared.
    const float* xa_b = xa + (size_t)b * N1_ * 3;
    for (int n = tid; n < N1_; n += THREADS) {
        s_xa[n * XSTRIDE + 0] = xa_b[n * 3 + 0];
        s_xa[n * XSTRIDE + 1] = xa_b[n * 3 + 1];
        s_xa[n * XSTRIDE + 2] = xa_b[n * 3 + 2];
        s_xa[n * XSTRIDE + 3] = 0.f;
    }
    // Zero slot 15 of every feature row.
    for (int n = tid; n < N1_; n += THREADS)
        s_ft[n * FSTRIDE + 15] = 0.f;
    // Stage features[b] with float4 loads (15360 floats = 3840 float4, 16B-aligned).
    {
        const float4* f4 = reinterpret_cast<const float4*>(feat + (size_t)b * N1_ * 15);
        for (int v = tid; v < N1_ * 15 / 4; v += THREADS) {
            float4 f = f4[v];
            int g = v * 4;
            int n = g / 15, s = g - n * 15;
            s_ft[n * FSTRIDE + s] = f.x;
            if (++s == 15) { s = 0; n++; }
            s_ft[n * FSTRIDE + s] = f.y;
            if (++s == 15) { s = 0; n++; }
            s_ft[n * FSTRIDE + s] = f.z;
            if (++s == 15) { s = 0; n++; }
            s_ft[n * FSTRIDE + s] = f.w;
        }
    }
    __syncthreads();

    // Per-lane target points (2 m's).
    const float* xt_b = xt + (size_t)b * N2_ * 3;
    const float t0r = xt_b[m0 * 3 + 0], t1r = xt_b[m0 * 3 + 1], t2r = xt_b[m0 * 3 + 2];
    const float u0r = xt_b[m1 * 3 + 0], u1r = xt_b[m1 * 3 + 1], u2r = xt_b[m1 * 3 + 2];

    const int n0 = wid * NCHUNK;

    uint64_t acc2[2][8];
    #pragma unroll
    for (int j = 0; j < 8; j++) { acc2[0][j] = 0ull; acc2[1][j] = 0ull; }
    float acc_s[2][15];
    #pragma unroll
    for (int i = 0; i < 15; i++) { acc_s[0][i] = 0.f; acc_s[1][i] = 0.f; }

    const int uni = s_uni;
    if (uni) {
        // w_c = exp2(-((a_c - t_c)*sgm)^2),  sgm = sqrt(-c0)
        const float sgm = sqrtf(-s_coef[0]);
        const float t0 = t0r * sgm, t1 = t1r * sgm, t2 = t2r * sgm;
        const float v0 = u0r * sgm, v1 = u1r * sgm, v2 = u2r * sgm;
        for (int n = n0; n < n0 + NCHUNK; n++) {
            float4 a = *reinterpret_cast<const float4*>(&s_xa[n * XSTRIDE]);  // broadcast
            // m0 weights
            float p0 = fmaf(a.x, sgm, -t0);
            float p1 = fmaf(a.y, sgm, -t1);
            float p2 = fmaf(a.z, sgm, -t2);
            float w0 = ex2f(p0 * -p0), w1 = ex2f(p1 * -p1), w2 = ex2f(p2 * -p2);
            // m1 weights
            float q0 = fmaf(a.x, sgm, -v0);
            float q1 = fmaf(a.y, sgm, -v1);
            float q2 = fmaf(a.z, sgm, -v2);
            float x0 = ex2f(q0 * -q0), x1 = ex2f(q1 * -q1), x2 = ex2f(q2 * -q2);
            // packed weight pattern over 16-slot row: A B C A B C A B
            uint64_t A0 = packf2(w0, w1), B0 = packf2(w2, w0), C0 = packf2(w1, w2);
            uint64_t A1 = packf2(x0, x1), B1 = packf2(x2, x0), C1 = packf2(x1, x2);
            // feature row: 4x LDS.128 (broadcast)
            const ulonglong2* fp = reinterpret_cast<const ulonglong2*>(&s_ft[n * FSTRIDE]);
            ulonglong2 pA = fp[0], pB = fp[1], pC = fp[2], pD = fp[3];
            acc2[0][0] = fma2(pA.x, A0, acc2[0][0]);
            acc2[0][1] = fma2(pA.y, B0, acc2[0][1]);
            acc2[0][2] = fma2(pB.x, C0, acc2[0][2]);
            acc2[0][3] = fma2(pB.y, A0, acc2[0][3]);
            acc2[0][4] = fma2(pC.x, B0, acc2[0][4]);
            acc2[0][5] = fma2(pC.y, C0, acc2[0][5]);
            acc2[0][6] = fma2(pD.x, A0, acc2[0][6]);
            acc2[0][7] = fma2(pD.y, B0, acc2[0][7]);   // slot15 feature = 0
            acc2[1][0] = fma2(pA.x, A1, acc2[1][0]);
            acc2[1][1] = fma2(pA.y, B1, acc2[1][1]);
            acc2[1][2] = fma2(pB.x, C1, acc2[1][2]);
            acc2[1][3] = fma2(pB.y, A1, acc2[1][3]);
            acc2[1][4] = fma2(pC.x, B1, acc2[1][4]);
            acc2[1][5] = fma2(pC.y, C1, acc2[1][5]);
            acc2[1][6] = fma2(pD.x, A1, acc2[1][6]);
            acc2[1][7] = fma2(pD.y, B1, acc2[1][7]);
        }
        #pragma unroll
        for (int t = 0; t < 2; t++) {
            #pragma unroll
            for (int j = 0; j < 8; j++) {
                float lo, hi;
                unpackf2(acc2[t][j], lo, hi);
                if (2*j     < 15) acc_s[t][2*j]     = lo;
                if (2*j + 1 < 15) acc_s[t][2*j + 1] = hi;
            }
        }
    } else {
        // General path: per-(k,c) bandwidth, scalar, 2 m's.
        float cf[15];
        #pragma unroll
        for (int i = 0; i < 15; i++) cf[i] = s_coef[i];
        for (int n = n0; n < n0 + NCHUNK; n++) {
            float4 a = *reinterpret_cast<const float4*>(&s_xa[n * XSTRIDE]);
            float d0 = a.x - t0r, d1 = a.y - t1r, d2 = a.z - t2r;
            float e0 = a.x - u0r, e1 = a.y - u1r, e2 = a.z - u2r;
            float qd0 = d0*d0, qd1 = d1*d1, qd2 = d2*d2;
            float qe0 = e0*e0, qe1 = e1*e1, qe2 = e2*e2;
            #pragma unroll
            for (int k = 0; k < 5; k++) {
                float fx = s_ft[n * FSTRIDE + k * 3 + 0];
                float fy = s_ft[n * FSTRIDE + k * 3 + 1];
                float fz = s_ft[n * FSTRIDE + k * 3 + 2];
                acc_s[0][k*3+0] = fmaf(fx, ex2f(qd0 * cf[k*3+0]), acc_s[0][k*3+0]);
                acc_s[0][k*3+1] = fmaf(fy, ex2f(qd1 * cf[k*3+1]), acc_s[0][k*3+1]);
                acc_s[0][k*3+2] = fmaf(fz, ex2f(qd2 * cf[k*3+2]), acc_s[0][k*3+2]);
                acc_s[1][k*3+0] = fmaf(fx, ex2f(qe0 * cf[k*3+0]), acc_s[1][k*3+0]);
                acc_s[1][k*3+1] = fmaf(fy, ex2f(qe1 * cf[k*3+1]), acc_s[1][k*3+1]);
                acc_s[1][k*3+2] = fmaf(fz, ex2f(qe2 * cf[k*3+2]), acc_s[1][k*3+2]);
            }
        }
    }

    // Cross-warp reduction: 16 partials per (m_loc, i). Reuse feature smem.
    __syncthreads();
    float* red = s_ft;                       // [16 warps][64 m][16] = 16384 floats
    {
        float* d0 = &red[(wid * 64 + lane) * 16];
        float* d1 = &red[(wid * 64 + 32 + lane) * 16];
        #pragma unroll
        for (int i = 0; i < 15; i++) { d0[i] = acc_s[0][i]; d1[i] = acc_s[1][i]; }
    }
    __syncthreads();

    // 960 outputs per block; 512 threads -> strided loop.
    for (int o = tid; o < M_BLK * 15; o += THREADS) {
        int m_loc = o / 15, i = o - m_loc * 15;
        float s = 0.f;
        #pragma unroll
        for (int w = 0; w < WARPS; w++)
            s += red[(w * 64 + m_loc) * 16 + i];
        out[((size_t)b * N2_ + m_base) * 15 + o] = s;
    }
}

extern "C" void kernel_launch(void* const* d_in, const int* in_sizes, int n_in,
                              void* d_out, int out_size)
{
    const float* xa   = (const float*)d_in[0];
    const float* feat = (const float*)d_in[1];
    const float* xt   = (const float*)d_in[2];
    const float* lstd = (const float*)d_in[3];
    float* out = (float*)d_out;

    const size_t smem = SMEM_FLOATS * sizeof(float);   // 80 KB dynamic
    cudaFuncSetAttribute(icgp_kernel, cudaFuncAttributeMaxDynamicSharedMemorySize, (int)smem);

    dim3 grid(N2_ / M_BLK, B_);   // (16, 8) = 128 blocks, single wave on 148 SMs
    icgp_kernel<<<grid, THREADS, smem>>>(xa, feat, xt, lstd, out);
}